// round 1
// baseline (speedup 1.0000x reference)
#include <cuda_runtime.h>

// Problem dims (fixed by reference setup_inputs)
#define B_DIM 8192
#define T_DIM 2048
#define H     20
#define G4    80          // 4*H gate rows
#define CTA_ROWS 64       // rows per CTA (32 f32x2 pairs)
#define PAIRS 32
#define NWARP 8
#define KPW   10          // gate rows per warp (8*10 = 80)

typedef unsigned long long u64;

// Scratch (allocation-free rule: __device__ globals)
__device__ float g_xT[(size_t)T_DIM * B_DIM];   // x transposed: [t][b]
__device__ float g_outT[(size_t)T_DIM * B_DIM]; // out transposed: [t][b]

// ---------------- f32x2 helpers ----------------
__device__ __forceinline__ u64 pk(float lo, float hi) {
    u64 r; asm("mov.b64 %0,{%1,%2};" : "=l"(r) : "f"(lo), "f"(hi)); return r;
}
__device__ __forceinline__ void upk(u64 v, float& lo, float& hi) {
    asm("mov.b64 {%0,%1},%2;" : "=f"(lo), "=f"(hi) : "l"(v));
}
__device__ __forceinline__ u64 fma2(u64 a, u64 b, u64 c) {
    u64 d; asm("fma.rn.f32x2 %0,%1,%2,%3;" : "=l"(d) : "l"(a), "l"(b), "l"(c)); return d;
}
__device__ __forceinline__ float rcpf(float x) {
    float r; asm("rcp.approx.f32 %0,%1;" : "=f"(r) : "f"(x)); return r;
}

// LSTM cell scalar math. 5 EX2 + 3 RCP per call.
// sigmoid(x) = 1/(1+e^-x); tanh(x) = 1 - 2/(1+e^{2x}).
// Args clamped at 40 so pairwise denominator products never overflow
// (max (1+e^40)^2 ~ 5.5e34 < FLT_MAX) and no inf*0 NaNs in the back-substitution.
__device__ __forceinline__ void cell(float ig, float fg, float gg, float og,
                                     float& c, float& h) {
    float ei = __expf(fminf(-ig, 40.f));
    float ef = __expf(fminf(-fg, 40.f));
    float eo = __expf(fminf(-og, 40.f));
    float eg = __expf(fminf(2.f * gg, 40.f));
    float a = 1.f + ei, b = 1.f + ef;      // sigmoid denoms for i, f
    float cd = 1.f + eo, d = 1.f + eg;     // sigmoid denom for o, tanh denom for g
    float r1 = rcpf(a * b);
    float si = r1 * b;                     // sigmoid(ig)
    float sf = r1 * a;                     // sigmoid(fg)
    float r2 = rcpf(cd * d);
    float so = r2 * d;                     // sigmoid(og)
    float tg = 1.f - 2.f * (r2 * cd);      // tanh(gg)
    float cn = sf * c + si * tg;
    float ec = __expf(fminf(2.f * cn, 40.f));
    float tc = 1.f - 2.f * rcpf(1.f + ec); // tanh(c_new)
    c = cn;
    h = so * tc;
}

// ---------------- transposes ----------------
__global__ void transpose_in(const float* __restrict__ in) {
    __shared__ float tile[32][33];
    int c0 = blockIdx.x * 32, r0 = blockIdx.y * 32;
    int tx = threadIdx.x, ty = threadIdx.y;
#pragma unroll
    for (int i = 0; i < 32; i += 8)
        tile[ty + i][tx] = in[(size_t)(r0 + ty + i) * T_DIM + c0 + tx];
    __syncthreads();
#pragma unroll
    for (int i = 0; i < 32; i += 8)
        g_xT[(size_t)(c0 + ty + i) * B_DIM + r0 + tx] = tile[tx][ty + i];
}

__global__ void transpose_out(float* __restrict__ out) {
    __shared__ float tile[32][33];
    int c0 = blockIdx.x * 32, r0 = blockIdx.y * 32;   // c over B, r over T
    int tx = threadIdx.x, ty = threadIdx.y;
#pragma unroll
    for (int i = 0; i < 32; i += 8)
        tile[ty + i][tx] = g_outT[(size_t)(r0 + ty + i) * B_DIM + c0 + tx];
    __syncthreads();
#pragma unroll
    for (int i = 0; i < 32; i += 8)
        out[(size_t)(c0 + ty + i) * T_DIM + r0 + tx] = tile[tx][ty + i];
}

// ---------------- main persistent LSTM kernel ----------------
__global__ __launch_bounds__(256, 1) void lstm_kernel(
    const float* __restrict__ W1, const float* __restrict__ b1,
    const float* __restrict__ W_ih, const float* __restrict__ W_hh,
    const float* __restrict__ b_ih, const float* __restrict__ b_hh,
    const float* __restrict__ W2, const float* __restrict__ b2)
{
    // Weights transposed + duplicated into f32x2: WT_s[u][k] = (W_hh[k][u], W_hh[k][u])
    __shared__ __align__(16) u64 WT_s[H][G4];        // 12.8 KB
    __shared__ u64 uv_u[G4], uv_v[G4];               // folded input-path coefficients
    __shared__ u64 w2_s[H];
    __shared__ float b2_s;
    __shared__ u64 gates_s[G4 * 33];                 // [k][pair], pad 33 vs 32
    __shared__ u64 h_s[H * 33];                      // [u][pair]

    const int tid  = threadIdx.x;
    const int lane = tid & 31;
    const int wid  = tid >> 5;
    const int rowbase = blockIdx.x * CTA_ROWS;

    // --- one-time setup ---
    for (int i = tid; i < H * G4; i += 256) {
        int u = i / G4, k = i % G4;
        float w = W_hh[k * H + u];
        WT_s[u][k] = pk(w, w);
    }
    if (tid < G4) {
        float su = 0.f, sv = 0.f;
        for (int u = 0; u < H; ++u) {
            float w = W_ih[tid * H + u];
            su += w * W1[u];
            sv += w * b1[u];
        }
        sv += b_ih[tid] + b_hh[tid];
        uv_u[tid] = pk(su, su);
        uv_v[tid] = pk(sv, sv);
    }
    if (tid < H) { float w = W2[tid]; w2_s[tid] = pk(w, w); }
    if (tid == 0) b2_s = b2[0];
    for (int i = tid; i < H * 33; i += 256) h_s[i] = 0ULL;
    __syncthreads();

    const int k0  = wid * KPW;   // phase-1 gate-row base for this warp
    const int sub = wid;         // phase-2 unit subset
    u64 c2[3] = {0ULL, 0ULL, 0ULL};  // cell state for units sub, sub+8, sub+16

    for (int t = 0; t < T_DIM; ++t) {
        // ---- phase 1: gates[k][pair] = v_k + x*u_k + sum_u W_hh[k][u]*h[u] ----
        float2 xv = ((const float2*)(g_xT + (size_t)t * B_DIM + rowbase))[lane];
        u64 x2 = pk(xv.x, xv.y);

        u64 h2[H];
#pragma unroll
        for (int u = 0; u < H; ++u) h2[u] = h_s[u * 33 + lane];

        u64 acc[KPW];
#pragma unroll
        for (int kk = 0; kk < KPW; ++kk)
            acc[kk] = fma2(x2, uv_u[k0 + kk], uv_v[k0 + kk]);

#pragma unroll
        for (int u = 0; u < H; ++u) {
            u64 hu = h2[u];
#pragma unroll
            for (int j = 0; j < KPW / 2; ++j) {
                ulonglong2 w = *(const ulonglong2*)&WT_s[u][k0 + 2 * j];
                acc[2 * j]     = fma2(w.x, hu, acc[2 * j]);
                acc[2 * j + 1] = fma2(w.y, hu, acc[2 * j + 1]);
            }
        }
#pragma unroll
        for (int kk = 0; kk < KPW; ++kk)
            gates_s[(k0 + kk) * 33 + lane] = acc[kk];
        __syncthreads();

        // ---- phase 2: elementwise cell update for units {sub, sub+8, sub+16} ----
#pragma unroll
        for (int j = 0; j < 3; ++j) {
            int u = sub + 8 * j;
            if (u < H) {
                float i0, i1, f0, f1, g0, g1, o0, o1;
                upk(gates_s[(u          ) * 33 + lane], i0, i1);
                upk(gates_s[(H   + u    ) * 33 + lane], f0, f1);
                upk(gates_s[(2*H + u    ) * 33 + lane], g0, g1);
                upk(gates_s[(3*H + u    ) * 33 + lane], o0, o1);
                float c0, c1; upk(c2[j], c0, c1);
                float h0, h1;
                cell(i0, f0, g0, o0, c0, h0);
                cell(i1, f1, g1, o1, c1, h1);
                c2[j] = pk(c0, c1);
                h_s[u * 33 + lane] = pk(h0, h1);
            }
        }
        __syncthreads();

        // ---- output row: out[t][b] = W2 . h_new + b2 (warp 0 only; safe:
        // h_s is not rewritten until everyone passes the NEXT phase-1 barrier) ----
        if (wid == 0) {
            u64 oacc = pk(b2_s, b2_s);
#pragma unroll
            for (int u = 0; u < H; ++u)
                oacc = fma2(w2_s[u], h_s[u * 33 + lane], oacc);
            float o0, o1; upk(oacc, o0, o1);
            ((float2*)(g_outT + (size_t)t * B_DIM + rowbase))[lane] =
                make_float2(o0, o1);
        }
    }
}

// ---------------- launcher ----------------
extern "C" void kernel_launch(void* const* d_in, const int* in_sizes, int n_in,
                              void* d_out, int out_size)
{
    const float* x    = (const float*)d_in[0];
    const float* W1   = (const float*)d_in[1];
    const float* b1   = (const float*)d_in[2];
    const float* W_ih = (const float*)d_in[3];
    const float* W_hh = (const float*)d_in[4];
    const float* b_ih = (const float*)d_in[5];
    const float* b_hh = (const float*)d_in[6];
    const float* W2   = (const float*)d_in[7];
    const float* b2   = (const float*)d_in[8];
    float* out = (float*)d_out;

    (void)in_sizes; (void)n_in; (void)out_size;

    // x[B][T] -> g_xT[T][B]
    transpose_in<<<dim3(T_DIM / 32, B_DIM / 32), dim3(32, 8)>>>(x);

    // recurrent scan: 128 CTAs x 256 threads, 64 rows per CTA
    lstm_kernel<<<B_DIM / CTA_ROWS, 256>>>(W1, b1, W_ih, W_hh, b_ih, b_hh, W2, b2);

    // g_outT[T][B] -> out[B][T]
    transpose_out<<<dim3(B_DIM / 32, T_DIM / 32), dim3(32, 8)>>>(out);
}

// round 2
// speedup vs baseline: 1.0717x; 1.0717x over previous
#include <cuda_runtime.h>

// Problem dims (fixed by reference setup_inputs)
#define B_DIM 8192
#define T_DIM 2048
#define H     20
#define G4    80          // 4*H gate rows
#define CTA_ROWS 64       // rows per CTA (32 f32x2 pairs)
#define NTHR  640         // 20 warps
#define KPW   4           // gate rows per warp (20*4 = 80)

typedef unsigned long long u64;

// Scratch (allocation-free rule: __device__ globals)
__device__ float g_xT[(size_t)T_DIM * B_DIM];   // x transposed: [t][b]
__device__ float g_outT[(size_t)T_DIM * B_DIM]; // out transposed: [t][b]

// ---------------- f32x2 helpers ----------------
__device__ __forceinline__ u64 pk(float lo, float hi) {
    u64 r; asm("mov.b64 %0,{%1,%2};" : "=l"(r) : "f"(lo), "f"(hi)); return r;
}
__device__ __forceinline__ void upk(u64 v, float& lo, float& hi) {
    asm("mov.b64 {%0,%1},%2;" : "=f"(lo), "=f"(hi) : "l"(v));
}
__device__ __forceinline__ u64 fma2(u64 a, u64 b, u64 c) {
    u64 d; asm("fma.rn.f32x2 %0,%1,%2,%3;" : "=l"(d) : "l"(a), "l"(b), "l"(c)); return d;
}
__device__ __forceinline__ float rcpf(float x) {
    float r; asm("rcp.approx.f32 %0,%1;" : "=f"(r) : "f"(x)); return r;
}

// LSTM cell scalar math. 5 EX2 + 3 RCP per call (accurate path, rel_err ~1e-6).
// sigmoid(x) = 1/(1+e^-x); tanh(x) = 1 - 2/(1+e^{2x}).
// Args clamped at 40 so pairwise denominator products never overflow.
__device__ __forceinline__ void cell(float ig, float fg, float gg, float og,
                                     float& c, float& h) {
    float ei = __expf(fminf(-ig, 40.f));
    float ef = __expf(fminf(-fg, 40.f));
    float eo = __expf(fminf(-og, 40.f));
    float eg = __expf(fminf(2.f * gg, 40.f));
    float a = 1.f + ei, b = 1.f + ef;      // sigmoid denoms for i, f
    float cd = 1.f + eo, d = 1.f + eg;     // sigmoid denom for o, tanh denom for g
    float r1 = rcpf(a * b);
    float si = r1 * b;                     // sigmoid(ig)
    float sf = r1 * a;                     // sigmoid(fg)
    float r2 = rcpf(cd * d);
    float so = r2 * d;                     // sigmoid(og)
    float tg = 1.f - 2.f * (r2 * cd);      // tanh(gg)
    float cn = sf * c + si * tg;
    float ec = __expf(fminf(2.f * cn, 40.f));
    float tc = 1.f - 2.f * rcpf(1.f + ec); // tanh(c_new)
    c = cn;
    h = so * tc;
}

// ---------------- transposes ----------------
__global__ void transpose_in(const float* __restrict__ in) {
    __shared__ float tile[32][33];
    int c0 = blockIdx.x * 32, r0 = blockIdx.y * 32;
    int tx = threadIdx.x, ty = threadIdx.y;
#pragma unroll
    for (int i = 0; i < 32; i += 8)
        tile[ty + i][tx] = in[(size_t)(r0 + ty + i) * T_DIM + c0 + tx];
    __syncthreads();
#pragma unroll
    for (int i = 0; i < 32; i += 8)
        g_xT[(size_t)(c0 + ty + i) * B_DIM + r0 + tx] = tile[tx][ty + i];
}

__global__ void transpose_out(float* __restrict__ out) {
    __shared__ float tile[32][33];
    int c0 = blockIdx.x * 32, r0 = blockIdx.y * 32;   // c over B, r over T
    int tx = threadIdx.x, ty = threadIdx.y;
#pragma unroll
    for (int i = 0; i < 32; i += 8)
        tile[ty + i][tx] = g_outT[(size_t)(r0 + ty + i) * B_DIM + c0 + tx];
    __syncthreads();
#pragma unroll
    for (int i = 0; i < 32; i += 8)
        out[(size_t)(c0 + ty + i) * T_DIM + r0 + tx] = tile[tx][ty + i];
}

// ---------------- main persistent LSTM kernel ----------------
// 128 CTAs x 640 threads (20 warps). CTA owns 64 batch rows = 32 f32x2 pairs.
// Phase 1: warp w computes gate rows [4w, 4w+4) for all 32 pairs (lane=pair).
// Phase 2: thread tid owns (unit u = tid>>5, pair = tid&31): 640 = 20*32 exact.
__global__ __launch_bounds__(NTHR, 1) void lstm_kernel(
    const float* __restrict__ W1, const float* __restrict__ b1,
    const float* __restrict__ W_ih, const float* __restrict__ W_hh,
    const float* __restrict__ b_ih, const float* __restrict__ b_hh,
    const float* __restrict__ W2, const float* __restrict__ b2)
{
    // Weights transposed + duplicated into f32x2: WT_s[u][k] = (W_hh[k][u], W_hh[k][u])
    __shared__ __align__(16) u64 WT_s[H][G4];        // 12.8 KB
    __shared__ u64 uv_u[G4], uv_v[G4];               // folded input-path coefficients
    __shared__ u64 w2_s[H];
    __shared__ float b2_s;
    __shared__ u64 gates_s[G4 * 33];                 // [k][pair], pad 33 vs 32
    __shared__ u64 h_s[H * 33];                      // [u][pair]

    const int tid  = threadIdx.x;
    const int lane = tid & 31;
    const int wid  = tid >> 5;
    const int rowbase = blockIdx.x * CTA_ROWS;

    // --- one-time setup ---
    for (int i = tid; i < H * G4; i += NTHR) {
        int u = i / G4, k = i % G4;
        float w = W_hh[k * H + u];
        WT_s[u][k] = pk(w, w);
    }
    if (tid < G4) {
        float su = 0.f, sv = 0.f;
        for (int u = 0; u < H; ++u) {
            float w = W_ih[tid * H + u];
            su += w * W1[u];
            sv += w * b1[u];
        }
        sv += b_ih[tid] + b_hh[tid];
        uv_u[tid] = pk(su, su);
        uv_v[tid] = pk(sv, sv);
    }
    if (tid < H) { float w = W2[tid]; w2_s[tid] = pk(w, w); }
    if (tid == 0) b2_s = b2[0];
    for (int i = tid; i < H * 33; i += NTHR) h_s[i] = 0ULL;
    __syncthreads();

    const int k0 = wid * KPW;     // phase-1 gate-row base for this warp
    const int u2 = wid;           // phase-2 unit (== tid>>5)
    u64 c2 = 0ULL;                // cell state pair for (u2, lane)

    // x prefetch pipeline
    const float2* xrow = (const float2*)(g_xT + rowbase) ;
    float2 xv = xrow[lane];       // t = 0 (row stride handled below via ptr math)

    for (int t = 0; t < T_DIM; ++t) {
        // issue next step's x load early (off critical path)
        float2 xnext = xv;
        if (t + 1 < T_DIM)
            xnext = ((const float2*)(g_xT + (size_t)(t + 1) * B_DIM + rowbase))[lane];

        // ---- phase 1: gates[k][pair] = v_k + x*u_k + sum_u W_hh[k][u]*h[u] ----
        u64 x2 = pk(xv.x, xv.y);

        u64 h2[H];
#pragma unroll
        for (int u = 0; u < H; ++u) h2[u] = h_s[u * 33 + lane];

        u64 acc[KPW];
#pragma unroll
        for (int kk = 0; kk < KPW; ++kk)
            acc[kk] = fma2(x2, uv_u[k0 + kk], uv_v[k0 + kk]);

#pragma unroll
        for (int u = 0; u < H; ++u) {
            u64 hu = h2[u];
            ulonglong2 w01 = *(const ulonglong2*)&WT_s[u][k0];
            ulonglong2 w23 = *(const ulonglong2*)&WT_s[u][k0 + 2];
            acc[0] = fma2(w01.x, hu, acc[0]);
            acc[1] = fma2(w01.y, hu, acc[1]);
            acc[2] = fma2(w23.x, hu, acc[2]);
            acc[3] = fma2(w23.y, hu, acc[3]);
        }
#pragma unroll
        for (int kk = 0; kk < KPW; ++kk)
            gates_s[(k0 + kk) * 33 + lane] = acc[kk];
        __syncthreads();

        // ---- phase 2: elementwise cell update, one (unit, pair) per thread ----
        {
            float i0, i1, f0, f1, g0, g1, o0, o1;
            upk(gates_s[(u2          ) * 33 + lane], i0, i1);
            upk(gates_s[(H   + u2    ) * 33 + lane], f0, f1);
            upk(gates_s[(2*H + u2    ) * 33 + lane], g0, g1);
            upk(gates_s[(3*H + u2    ) * 33 + lane], o0, o1);
            float cc0, cc1; upk(c2, cc0, cc1);
            float hh0, hh1;
            cell(i0, f0, g0, o0, cc0, hh0);
            cell(i1, f1, g1, o1, cc1, hh1);
            c2 = pk(cc0, cc1);
            h_s[u2 * 33 + lane] = pk(hh0, hh1);
        }
        __syncthreads();

        // ---- output row: out[t][b] = W2 . h_new + b2 (warp 0; h_s stable
        // until everyone passes the NEXT phase-1 barrier) ----
        if (wid == 0) {
            u64 oacc = pk(b2_s, b2_s);
#pragma unroll
            for (int u = 0; u < H; ++u)
                oacc = fma2(w2_s[u], h_s[u * 33 + lane], oacc);
            float o0, o1; upk(oacc, o0, o1);
            ((float2*)(g_outT + (size_t)t * B_DIM + rowbase))[lane] =
                make_float2(o0, o1);
        }

        xv = xnext;
    }
    (void)xrow;
}

// ---------------- launcher ----------------
extern "C" void kernel_launch(void* const* d_in, const int* in_sizes, int n_in,
                              void* d_out, int out_size)
{
    const float* x    = (const float*)d_in[0];
    const float* W1   = (const float*)d_in[1];
    const float* b1   = (const float*)d_in[2];
    const float* W_ih = (const float*)d_in[3];
    const float* W_hh = (const float*)d_in[4];
    const float* b_ih = (const float*)d_in[5];
    const float* b_hh = (const float*)d_in[6];
    const float* W2   = (const float*)d_in[7];
    const float* b2   = (const float*)d_in[8];
    float* out = (float*)d_out;

    (void)in_sizes; (void)n_in; (void)out_size;

    // x[B][T] -> g_xT[T][B]
    transpose_in<<<dim3(T_DIM / 32, B_DIM / 32), dim3(32, 8)>>>(x);

    // recurrent scan: 128 CTAs x 640 threads, 64 rows per CTA
    lstm_kernel<<<B_DIM / CTA_ROWS, NTHR>>>(W1, b1, W_ih, W_hh, b_ih, b_hh, W2, b2);

    // g_outT[T][B] -> out[B][T]
    transpose_out<<<dim3(B_DIM / 32, T_DIM / 32), dim3(32, 8)>>>(out);
}

// round 3
// speedup vs baseline: 1.2186x; 1.1371x over previous
#include <cuda_runtime.h>

// Problem dims (fixed by reference setup_inputs)
#define B_DIM 8192
#define T_DIM 2048
#define H     20
#define G4    80          // 4*H gate rows
#define CTA_ROWS 64       // rows per CTA (32 f32x2 pairs)
#define NTHR  640         // 20 warps; warp w owns unit w

typedef unsigned long long u64;

// Scratch (allocation-free rule: __device__ globals)
__device__ float g_xT[(size_t)T_DIM * B_DIM];   // x transposed: [t][b]
__device__ float g_outT[(size_t)T_DIM * B_DIM]; // out transposed: [t][b]

// ---------------- f32x2 helpers ----------------
__device__ __forceinline__ u64 pk(float lo, float hi) {
    u64 r; asm("mov.b64 %0,{%1,%2};" : "=l"(r) : "f"(lo), "f"(hi)); return r;
}
__device__ __forceinline__ void upk(u64 v, float& lo, float& hi) {
    asm("mov.b64 {%0,%1},%2;" : "=f"(lo), "=f"(hi) : "l"(v));
}
__device__ __forceinline__ u64 fma2(u64 a, u64 b, u64 c) {
    u64 d; asm("fma.rn.f32x2 %0,%1,%2,%3;" : "=l"(d) : "l"(a), "l"(b), "l"(c)); return d;
}
__device__ __forceinline__ float rcpf(float x) {
    float r; asm("rcp.approx.f32 %0,%1;" : "=f"(r) : "f"(x)); return r;
}

// LSTM cell scalar math. 5 EX2 + 3 RCP per call (accurate path, rel_err ~1e-6).
// sigmoid(x) = 1/(1+e^-x); tanh(x) = 1 - 2/(1+e^{2x}).
// Args clamped at 40 so pairwise denominator products never overflow.
__device__ __forceinline__ void cell(float ig, float fg, float gg, float og,
                                     float& c, float& h) {
    float ei = __expf(fminf(-ig, 40.f));
    float ef = __expf(fminf(-fg, 40.f));
    float eo = __expf(fminf(-og, 40.f));
    float eg = __expf(fminf(2.f * gg, 40.f));
    float a = 1.f + ei, b = 1.f + ef;
    float cd = 1.f + eo, d = 1.f + eg;
    float r1 = rcpf(a * b);
    float si = r1 * b;
    float sf = r1 * a;
    float r2 = rcpf(cd * d);
    float so = r2 * d;
    float tg = 1.f - 2.f * (r2 * cd);
    float cn = sf * c + si * tg;
    float ec = __expf(fminf(2.f * cn, 40.f));
    float tc = 1.f - 2.f * rcpf(1.f + ec);
    c = cn;
    h = so * tc;
}

// ---------------- transposes ----------------
__global__ void transpose_in(const float* __restrict__ in) {
    __shared__ float tile[32][33];
    int c0 = blockIdx.x * 32, r0 = blockIdx.y * 32;
    int tx = threadIdx.x, ty = threadIdx.y;
#pragma unroll
    for (int i = 0; i < 32; i += 8)
        tile[ty + i][tx] = in[(size_t)(r0 + ty + i) * T_DIM + c0 + tx];
    __syncthreads();
#pragma unroll
    for (int i = 0; i < 32; i += 8)
        g_xT[(size_t)(c0 + ty + i) * B_DIM + r0 + tx] = tile[tx][ty + i];
}

__global__ void transpose_out(float* __restrict__ out) {
    __shared__ float tile[32][33];
    int c0 = blockIdx.x * 32, r0 = blockIdx.y * 32;
    int tx = threadIdx.x, ty = threadIdx.y;
#pragma unroll
    for (int i = 0; i < 32; i += 8)
        tile[ty + i][tx] = g_outT[(size_t)(r0 + ty + i) * B_DIM + c0 + tx];
    __syncthreads();
#pragma unroll
    for (int i = 0; i < 32; i += 8)
        out[(size_t)(c0 + ty + i) * T_DIM + r0 + tx] = tile[tx][ty + i];
}

// ---------------- main persistent LSTM kernel ----------------
// 128 CTAs x 640 threads (20 warps). CTA owns 64 batch rows = 32 f32x2 pairs.
// Warp w owns UNIT w: computes gate rows {i,f,g,o} of unit w for all 32 pairs
// (lane = pair), does the cell update on its own registers (no gate smem, no
// intra-step barrier), and publishes h[w][*] into a double-buffered h_s.
// Exactly ONE __syncthreads per timestep.
__global__ __launch_bounds__(NTHR, 1) void lstm_kernel(
    const float* __restrict__ W1, const float* __restrict__ b1,
    const float* __restrict__ W_ih, const float* __restrict__ W_hh,
    const float* __restrict__ b_ih, const float* __restrict__ b_hh,
    const float* __restrict__ W2, const float* __restrict__ b2)
{
    // WT2_s[u'][w*4+g] = (W_hh[g*H+w][u'], same): the 4 gate rows of unit w
    // are contiguous -> 2x LDS.128 per u' per warp.
    __shared__ __align__(16) u64 WT2_s[H][G4];       // 12.8 KB
    __shared__ __align__(16) u64 uvz[G4 * 2];        // [w*8 + 2g] = u, [..+1] = v
    __shared__ u64 w2_s[H];
    __shared__ float b2_s;
    __shared__ u64 h_s[2][H][33];                    // double-buffered [buf][u][pair]

    const int tid  = threadIdx.x;
    const int lane = tid & 31;
    const int wid  = tid >> 5;                       // == unit owned by this warp
    const int rowbase = blockIdx.x * CTA_ROWS;

    // --- one-time setup ---
    for (int i = tid; i < H * G4; i += NTHR) {
        int u = i / G4, j = i % G4;
        int w = j >> 2, g = j & 3;                   // unit w, gate g (i,f,g,o)
        float wv = W_hh[(g * H + w) * H + u];
        WT2_s[u][j] = pk(wv, wv);
    }
    if (tid < G4) {
        int w = tid >> 2, g = tid & 3;
        int k = g * H + w;                           // original gate-row index
        float su = 0.f, sv = 0.f;
        for (int u = 0; u < H; ++u) {
            float wv = W_ih[k * H + u];
            su += wv * W1[u];
            sv += wv * b1[u];
        }
        sv += b_ih[k] + b_hh[k];
        uvz[w * 8 + 2 * g]     = pk(su, su);
        uvz[w * 8 + 2 * g + 1] = pk(sv, sv);
    }
    if (tid < H) { float wv = W2[tid]; w2_s[tid] = pk(wv, wv); }
    if (tid == 0) b2_s = b2[0];
    for (int i = tid; i < H * 33; i += NTHR) h_s[0][0][i] = 0ULL;
    __syncthreads();

    // hoist loop-invariant input-path coefficients into registers
    const u64 u_i = uvz[wid * 8 + 0], v_i = uvz[wid * 8 + 1];
    const u64 u_f = uvz[wid * 8 + 2], v_f = uvz[wid * 8 + 3];
    const u64 u_g = uvz[wid * 8 + 4], v_g = uvz[wid * 8 + 5];
    const u64 u_o = uvz[wid * 8 + 6], v_o = uvz[wid * 8 + 7];

    u64 c2 = 0ULL;                                   // cell state pair (unit wid, lane)

    // x prefetch pipeline
    float2 xv = ((const float2*)(g_xT + rowbase))[lane];

    for (int t = 0; t < T_DIM; ++t) {
        const int cur = t & 1, nxt = cur ^ 1;

        // prefetch next x (off critical path)
        float2 xnext = xv;
        if (t + 1 < T_DIM)
            xnext = ((const float2*)(g_xT + (size_t)(t + 1) * B_DIM + rowbase))[lane];

        // ---- read full h vector (buffer cur) ----
        u64 h2[H];
#pragma unroll
        for (int u = 0; u < H; ++u) h2[u] = h_s[cur][u][lane];

        // ---- out[t-1] = W2 . h + b2 : warp 0 reuses its h2 registers ----
        if (wid == 0 && t > 0) {
            u64 oacc = pk(b2_s, b2_s);
#pragma unroll
            for (int u = 0; u < H; ++u)
                oacc = fma2(w2_s[u], h2[u], oacc);
            float o0, o1; upk(oacc, o0, o1);
            ((float2*)(g_outT + (size_t)(t - 1) * B_DIM + rowbase))[lane] =
                make_float2(o0, o1);
        }

        // ---- gates for unit wid (4 rows), all 32 pairs ----
        u64 x2 = pk(xv.x, xv.y);
        u64 acc_i = fma2(x2, u_i, v_i);
        u64 acc_f = fma2(x2, u_f, v_f);
        u64 acc_g = fma2(x2, u_g, v_g);
        u64 acc_o = fma2(x2, u_o, v_o);

#pragma unroll
        for (int u = 0; u < H; ++u) {
            u64 hu = h2[u];
            ulonglong2 wa = *(const ulonglong2*)&WT2_s[u][wid * 4];
            ulonglong2 wb = *(const ulonglong2*)&WT2_s[u][wid * 4 + 2];
            acc_i = fma2(wa.x, hu, acc_i);
            acc_f = fma2(wa.y, hu, acc_f);
            acc_g = fma2(wb.x, hu, acc_g);
            acc_o = fma2(wb.y, hu, acc_o);
        }

        // ---- cell update in-warp (no barrier needed before this) ----
        float i0, i1, f0, f1, g0, g1, o0, o1;
        upk(acc_i, i0, i1); upk(acc_f, f0, f1);
        upk(acc_g, g0, g1); upk(acc_o, o0, o1);
        float cc0, cc1; upk(c2, cc0, cc1);
        float hh0, hh1;
        cell(i0, f0, g0, o0, cc0, hh0);
        cell(i1, f1, g1, o1, cc1, hh1);
        c2 = pk(cc0, cc1);
        h_s[nxt][wid][lane] = pk(hh0, hh1);

        // ---- single barrier: publish h[t+1], protect buffer swap ----
        __syncthreads();

        xv = xnext;
    }

    // final output row: out[T-1] from buffer (T_DIM & 1)
    if (wid == 0) {
        const int cur = T_DIM & 1;
        u64 oacc = pk(b2_s, b2_s);
#pragma unroll
        for (int u = 0; u < H; ++u)
            oacc = fma2(w2_s[u], h_s[cur][u][lane], oacc);
        float o0, o1; upk(oacc, o0, o1);
        ((float2*)(g_outT + (size_t)(T_DIM - 1) * B_DIM + rowbase))[lane] =
            make_float2(o0, o1);
    }
}

// ---------------- launcher ----------------
extern "C" void kernel_launch(void* const* d_in, const int* in_sizes, int n_in,
                              void* d_out, int out_size)
{
    const float* x    = (const float*)d_in[0];
    const float* W1   = (const float*)d_in[1];
    const float* b1   = (const float*)d_in[2];
    const float* W_ih = (const float*)d_in[3];
    const float* W_hh = (const float*)d_in[4];
    const float* b_ih = (const float*)d_in[5];
    const float* b_hh = (const float*)d_in[6];
    const float* W2   = (const float*)d_in[7];
    const float* b2   = (const float*)d_in[8];
    float* out = (float*)d_out;

    (void)in_sizes; (void)n_in; (void)out_size;

    // x[B][T] -> g_xT[T][B]
    transpose_in<<<dim3(T_DIM / 32, B_DIM / 32), dim3(32, 8)>>>(x);

    // recurrent scan: 128 CTAs x 640 threads, 64 rows per CTA, unit-per-warp
    lstm_kernel<<<B_DIM / CTA_ROWS, NTHR>>>(W1, b1, W_ih, W_hh, b_ih, b_hh, W2, b2);

    // g_outT[T][B] -> out[B][T]
    transpose_out<<<dim3(B_DIM / 32, T_DIM / 32), dim3(32, 8)>>>(out);
}

// round 4
// speedup vs baseline: 1.5455x; 1.2682x over previous
#include <cuda_runtime.h>

// Problem dims (fixed by reference setup_inputs)
#define B_DIM 8192
#define T_DIM 2048
#define H     20
#define CTA_ROWS 64       // batch rows per CTA
#define NTHR  640         // 20 warps = 10 unit-pairs x 2 row-halves

typedef unsigned long long u64;

// Scratch (allocation-free rule: __device__ globals)
__device__ float g_xT[(size_t)T_DIM * B_DIM];   // x transposed: [t][b]
__device__ float g_outT[(size_t)T_DIM * B_DIM]; // out transposed: [t][b]

// ---------------- f32x2 helpers ----------------
__device__ __forceinline__ u64 pk(float lo, float hi) {
    u64 r; asm("mov.b64 %0,{%1,%2};" : "=l"(r) : "f"(lo), "f"(hi)); return r;
}
__device__ __forceinline__ void upk(u64 v, float& lo, float& hi) {
    asm("mov.b64 {%0,%1},%2;" : "=f"(lo), "=f"(hi) : "l"(v));
}
__device__ __forceinline__ u64 fma2(u64 a, u64 b, u64 c) {
    u64 d; asm("fma.rn.f32x2 %0,%1,%2,%3;" : "=l"(d) : "l"(a), "l"(b), "l"(c)); return d;
}
__device__ __forceinline__ float tanh_a(float x) {
    float r; asm("tanh.approx.f32 %0,%1;" : "=f"(r) : "f"(x)); return r;
}

// LSTM cell via MUFU.TANH: 5 MUFU + ~9 FMA-pipe ops.
// sigmoid(x) = 0.5*tanh(0.5x) + 0.5  (exact identity; tanh is the approx part)
__device__ __forceinline__ void cell(float ig, float fg, float gg, float og,
                                     float& c, float& h) {
    float si = fmaf(0.5f, tanh_a(0.5f * ig), 0.5f);
    float sf = fmaf(0.5f, tanh_a(0.5f * fg), 0.5f);
    float so = fmaf(0.5f, tanh_a(0.5f * og), 0.5f);
    float tg = tanh_a(gg);
    float cn = sf * c + si * tg;
    float tc = tanh_a(cn);
    c = cn;
    h = so * tc;
}

// ---------------- transposes ----------------
__global__ void transpose_in(const float* __restrict__ in) {
    __shared__ float tile[32][33];
    int c0 = blockIdx.x * 32, r0 = blockIdx.y * 32;
    int tx = threadIdx.x, ty = threadIdx.y;
#pragma unroll
    for (int i = 0; i < 32; i += 8)
        tile[ty + i][tx] = in[(size_t)(r0 + ty + i) * T_DIM + c0 + tx];
    __syncthreads();
#pragma unroll
    for (int i = 0; i < 32; i += 8)
        g_xT[(size_t)(c0 + ty + i) * B_DIM + r0 + tx] = tile[tx][ty + i];
}

__global__ void transpose_out(float* __restrict__ out) {
    __shared__ float tile[32][33];
    int c0 = blockIdx.x * 32, r0 = blockIdx.y * 32;
    int tx = threadIdx.x, ty = threadIdx.y;
#pragma unroll
    for (int i = 0; i < 32; i += 8)
        tile[ty + i][tx] = g_outT[(size_t)(r0 + ty + i) * B_DIM + c0 + tx];
    __syncthreads();
#pragma unroll
    for (int i = 0; i < 32; i += 8)
        out[(size_t)(c0 + ty + i) * T_DIM + r0 + tx] = tile[tx][ty + i];
}

// ---------------- main persistent LSTM kernel ----------------
// 128 CTAs x 640 threads. CTA owns 64 batch rows.
// Warp wid = up*2+rg owns UNIT PAIR {2up, 2up+1} for rows [rg*32, rg*32+32).
// Lane = row within the half. f32x2 packs (unit a, unit b) of the same gate.
// Weights carry two distinct values per u64 (no duplication); h is scalar.
// One __syncthreads per timestep (double-buffered h).
__global__ __launch_bounds__(NTHR, 1) void lstm_kernel(
    const float* __restrict__ W1, const float* __restrict__ b1,
    const float* __restrict__ W_ih, const float* __restrict__ W_hh,
    const float* __restrict__ b_ih, const float* __restrict__ b_hh,
    const float* __restrict__ W2, const float* __restrict__ b2)
{
    // WP_s[u][up*4 + g] = (W_hh[g*H+2up][u], W_hh[g*H+2up+1][u])
    __shared__ __align__(16) u64 WP_s[H][40];        // 6.4 KB
    __shared__ __align__(16) u64 uvz[80];            // [up*8+2g]=u-pair, [+1]=v-pair
    __shared__ float w2f[H];
    __shared__ float b2_s;
    __shared__ float h_s[2][H][66];                  // [buf][u][row], pad 66

    const int tid  = threadIdx.x;
    const int lane = tid & 31;
    const int wid  = tid >> 5;
    const int up   = wid >> 1;                       // unit pair index 0..9
    const int rg   = wid & 1;                        // row half 0/1
    const int row  = rg * 32 + lane;                 // row within CTA
    const int rowbase = blockIdx.x * CTA_ROWS;

    // --- one-time setup ---
    for (int i = tid; i < H * 40; i += NTHR) {
        int u = i / 40, j = i % 40;
        int p = j >> 2, g = j & 3;                   // unit pair p, gate g
        float wa = W_hh[(g * H + 2 * p    ) * H + u];
        float wb = W_hh[(g * H + 2 * p + 1) * H + u];
        WP_s[u][j] = pk(wa, wb);
    }
    if (tid < 40) {
        int p = tid >> 2, g = tid & 3;
        float su[2], sv[2];
#pragma unroll
        for (int s = 0; s < 2; ++s) {
            int k = g * H + 2 * p + s;               // original gate-row index
            float a = 0.f, bsum = 0.f;
            for (int u = 0; u < H; ++u) {
                float wv = W_ih[k * H + u];
                a    += wv * W1[u];
                bsum += wv * b1[u];
            }
            su[s] = a;
            sv[s] = bsum + b_ih[k] + b_hh[k];
        }
        uvz[p * 8 + 2 * g]     = pk(su[0], su[1]);
        uvz[p * 8 + 2 * g + 1] = pk(sv[0], sv[1]);
    }
    if (tid < H) w2f[tid] = W2[tid];
    if (tid == 0) b2_s = b2[0];
    for (int i = tid; i < H * 66; i += NTHR) h_s[0][0][i] = 0.f;
    __syncthreads();

    // hoist loop-invariant input-path coefficient pairs into registers
    const u64 u_i = uvz[up * 8 + 0], v_i = uvz[up * 8 + 1];
    const u64 u_f = uvz[up * 8 + 2], v_f = uvz[up * 8 + 3];
    const u64 u_g = uvz[up * 8 + 4], v_g = uvz[up * 8 + 5];
    const u64 u_o = uvz[up * 8 + 6], v_o = uvz[up * 8 + 7];

    u64 c2 = 0ULL;    // cell state (unit 2up, unit 2up+1) for this row

    // x prefetch pipeline (scalar per lane/row)
    float xv = g_xT[(size_t)0 * B_DIM + rowbase + row];

    for (int t = 0; t < T_DIM; ++t) {
        const int cur = t & 1, nxt = cur ^ 1;

        // prefetch next x (off critical path)
        float xnext = xv;
        if (t + 1 < T_DIM)
            xnext = g_xT[(size_t)(t + 1) * B_DIM + rowbase + row];

        // ---- gates for units {2up, 2up+1}, this row ----
        u64 xp = pk(xv, xv);
        u64 acc_i = fma2(xp, u_i, v_i);
        u64 acc_f = fma2(xp, u_f, v_f);
        u64 acc_g = fma2(xp, u_g, v_g);
        u64 acc_o = fma2(xp, u_o, v_o);

#pragma unroll
        for (int u = 0; u < H; ++u) {
            float hv = h_s[cur][u][row];             // scalar LDS.32, conflict-free
            u64 hp = pk(hv, hv);
            ulonglong2 wa = *(const ulonglong2*)&WP_s[u][up * 4];
            ulonglong2 wb = *(const ulonglong2*)&WP_s[u][up * 4 + 2];
            acc_i = fma2(wa.x, hp, acc_i);
            acc_f = fma2(wa.y, hp, acc_f);
            acc_g = fma2(wb.x, hp, acc_g);
            acc_o = fma2(wb.y, hp, acc_o);
        }

        // ---- out[t-1] = W2 . h + b2 : warps 0,1 only (h_s[cur] stable) ----
        if (wid < 2 && t > 0) {
            float oacc = b2_s;
#pragma unroll
            for (int u = 0; u < H; ++u)
                oacc = fmaf(w2f[u], h_s[cur][u][row], oacc);
            g_outT[(size_t)(t - 1) * B_DIM + rowbase + row] = oacc;
        }

        // ---- cell update in-warp (no barrier before this) ----
        float ia, ib, fa, fb, ga, gb, oa, ob;
        upk(acc_i, ia, ib); upk(acc_f, fa, fb);
        upk(acc_g, ga, gb); upk(acc_o, oa, ob);
        float ca, cb; upk(c2, ca, cb);
        float ha, hb;
        cell(ia, fa, ga, oa, ca, ha);
        cell(ib, fb, gb, ob, cb, hb);
        c2 = pk(ca, cb);
        h_s[nxt][2 * up    ][row] = ha;
        h_s[nxt][2 * up + 1][row] = hb;

        // ---- single barrier: publish h, protect buffer swap ----
        __syncthreads();

        xv = xnext;
    }

    // final output row: out[T-1] from buffer (T_DIM & 1)
    if (wid < 2) {
        const int cur = T_DIM & 1;
        float oacc = b2_s;
#pragma unroll
        for (int u = 0; u < H; ++u)
            oacc = fmaf(w2f[u], h_s[cur][u][row], oacc);
        g_outT[(size_t)(T_DIM - 1) * B_DIM + rowbase + row] = oacc;
    }
}

// ---------------- launcher ----------------
extern "C" void kernel_launch(void* const* d_in, const int* in_sizes, int n_in,
                              void* d_out, int out_size)
{
    const float* x    = (const float*)d_in[0];
    const float* W1   = (const float*)d_in[1];
    const float* b1   = (const float*)d_in[2];
    const float* W_ih = (const float*)d_in[3];
    const float* W_hh = (const float*)d_in[4];
    const float* b_ih = (const float*)d_in[5];
    const float* b_hh = (const float*)d_in[6];
    const float* W2   = (const float*)d_in[7];
    const float* b2   = (const float*)d_in[8];
    float* out = (float*)d_out;

    (void)in_sizes; (void)n_in; (void)out_size;

    // x[B][T] -> g_xT[T][B]
    transpose_in<<<dim3(T_DIM / 32, B_DIM / 32), dim3(32, 8)>>>(x);

    // recurrent scan: 128 CTAs x 640 threads, gate-pair packed
    lstm_kernel<<<B_DIM / CTA_ROWS, NTHR>>>(W1, b1, W_ih, W_hh, b_ih, b_hh, W2, b2);

    // g_outT[T][B] -> out[B][T]
    transpose_out<<<dim3(B_DIM / 32, T_DIM / 32), dim3(32, 8)>>>(out);
}

// round 5
// speedup vs baseline: 1.8888x; 1.2222x over previous
#include <cuda_runtime.h>

// Problem dims (fixed by reference setup_inputs)
#define B_DIM 8192
#define T_DIM 2048
#define H     20
#define CTA_ROWS 64       // batch rows per CTA
#define NTHR  320         // 10 warps; warp w = unit-pair w; lane carries 2 rows

typedef unsigned long long u64;

// Scratch (allocation-free rule: __device__ globals)
__device__ float g_xT[(size_t)T_DIM * B_DIM];   // x transposed: [t][b]
__device__ float g_outT[(size_t)T_DIM * B_DIM]; // out transposed: [t][b]

// ---------------- f32x2 helpers ----------------
__device__ __forceinline__ u64 pk(float lo, float hi) {
    u64 r; asm("mov.b64 %0,{%1,%2};" : "=l"(r) : "f"(lo), "f"(hi)); return r;
}
__device__ __forceinline__ void upk(u64 v, float& lo, float& hi) {
    asm("mov.b64 {%0,%1},%2;" : "=f"(lo), "=f"(hi) : "l"(v));
}
__device__ __forceinline__ u64 fma2(u64 a, u64 b, u64 c) {
    u64 d; asm("fma.rn.f32x2 %0,%1,%2,%3;" : "=l"(d) : "l"(a), "l"(b), "l"(c)); return d;
}
__device__ __forceinline__ float tanh_a(float x) {
    float r; asm("tanh.approx.f32 %0,%1;" : "=f"(r) : "f"(x)); return r;
}

// LSTM cell via MUFU.TANH: 5 MUFU + ~9 FMA-pipe ops.
// sigmoid(x) = 0.5*tanh(0.5x) + 0.5
__device__ __forceinline__ void cell(float ig, float fg, float gg, float og,
                                     float& c, float& h) {
    float si = fmaf(0.5f, tanh_a(0.5f * ig), 0.5f);
    float sf = fmaf(0.5f, tanh_a(0.5f * fg), 0.5f);
    float so = fmaf(0.5f, tanh_a(0.5f * og), 0.5f);
    float tg = tanh_a(gg);
    float cn = sf * c + si * tg;
    float tc = tanh_a(cn);
    c = cn;
    h = so * tc;
}

// ---------------- transposes ----------------
__global__ void transpose_in(const float* __restrict__ in) {
    __shared__ float tile[32][33];
    int c0 = blockIdx.x * 32, r0 = blockIdx.y * 32;
    int tx = threadIdx.x, ty = threadIdx.y;
#pragma unroll
    for (int i = 0; i < 32; i += 8)
        tile[ty + i][tx] = in[(size_t)(r0 + ty + i) * T_DIM + c0 + tx];
    __syncthreads();
#pragma unroll
    for (int i = 0; i < 32; i += 8)
        g_xT[(size_t)(c0 + ty + i) * B_DIM + r0 + tx] = tile[tx][ty + i];
}

__global__ void transpose_out(float* __restrict__ out) {
    __shared__ float tile[32][33];
    int c0 = blockIdx.x * 32, r0 = blockIdx.y * 32;
    int tx = threadIdx.x, ty = threadIdx.y;
#pragma unroll
    for (int i = 0; i < 32; i += 8)
        tile[ty + i][tx] = g_outT[(size_t)(r0 + ty + i) * B_DIM + c0 + tx];
    __syncthreads();
#pragma unroll
    for (int i = 0; i < 32; i += 8)
        out[(size_t)(c0 + ty + i) * T_DIM + r0 + tx] = tile[tx][ty + i];
}

// ---------------- main persistent LSTM kernel ----------------
// 128 CTAs x 320 threads (10 warps). CTA owns 64 batch rows.
// Warp up owns UNIT PAIR {2up, 2up+1}. Lane owns rows {2*lane, 2*lane+1}.
// f32x2 packs (unit a, unit b) of the same gate; two accumulator sets (row A/B).
// Weights carry two distinct values per u64 (no duplication).
// One __syncthreads per timestep (double-buffered h).
__global__ __launch_bounds__(NTHR, 1) void lstm_kernel(
    const float* __restrict__ W1, const float* __restrict__ b1,
    const float* __restrict__ W_ih, const float* __restrict__ W_hh,
    const float* __restrict__ b_ih, const float* __restrict__ b_hh,
    const float* __restrict__ W2, const float* __restrict__ b2)
{
    // WP_s[u][up*4 + g] = (W_hh[g*H+2up][u], W_hh[g*H+2up+1][u])
    __shared__ __align__(16) u64 WP_s[H][40];        // 6.4 KB
    __shared__ __align__(16) u64 uvz[80];            // [up*8+2g]=u-pair, [+1]=v-pair
    __shared__ u64 w2p[H];                           // (W2[u], W2[u]) duplicated
    __shared__ float b2_s;
    __shared__ __align__(8) float h_s[2][H][CTA_ROWS]; // [buf][u][row]

    const int tid  = threadIdx.x;
    const int lane = tid & 31;
    const int up   = tid >> 5;                       // unit pair index 0..9
    const int rowbase = blockIdx.x * CTA_ROWS;
    const int rA = 2 * lane;                         // rows owned by this lane

    // --- one-time setup ---
    for (int i = tid; i < H * 40; i += NTHR) {
        int u = i / 40, j = i % 40;
        int p = j >> 2, g = j & 3;                   // unit pair p, gate g
        float wa = W_hh[(g * H + 2 * p    ) * H + u];
        float wb = W_hh[(g * H + 2 * p + 1) * H + u];
        WP_s[u][j] = pk(wa, wb);
    }
    if (tid < 40) {
        int p = tid >> 2, g = tid & 3;
        float su[2], sv[2];
#pragma unroll
        for (int s = 0; s < 2; ++s) {
            int k = g * H + 2 * p + s;               // original gate-row index
            float a = 0.f, bsum = 0.f;
            for (int u = 0; u < H; ++u) {
                float wv = W_ih[k * H + u];
                a    += wv * W1[u];
                bsum += wv * b1[u];
            }
            su[s] = a;
            sv[s] = bsum + b_ih[k] + b_hh[k];
        }
        uvz[p * 8 + 2 * g]     = pk(su[0], su[1]);
        uvz[p * 8 + 2 * g + 1] = pk(sv[0], sv[1]);
    }
    if (tid < H) { float wv = W2[tid]; w2p[tid] = pk(wv, wv); }
    if (tid == 0) b2_s = b2[0];
    for (int i = tid; i < 2 * H * CTA_ROWS; i += NTHR) h_s[0][0][i] = 0.f;
    __syncthreads();

    // hoist loop-invariant input-path coefficient pairs into registers
    const u64 u_i = uvz[up * 8 + 0], v_i = uvz[up * 8 + 1];
    const u64 u_f = uvz[up * 8 + 2], v_f = uvz[up * 8 + 3];
    const u64 u_g = uvz[up * 8 + 4], v_g = uvz[up * 8 + 5];
    const u64 u_o = uvz[up * 8 + 6], v_o = uvz[up * 8 + 7];

    u64 cA = 0ULL, cB = 0ULL;   // cell state (u0,u1) for row A and row B

    // x prefetch pipeline: float2 covers this lane's two rows
    float2 xv = *(const float2*)(g_xT + rowbase + rA);

    for (int t = 0; t < T_DIM; ++t) {
        const int cur = t & 1, nxt = cur ^ 1;

        // prefetch next x (off critical path)
        float2 xnext = xv;
        if (t + 1 < T_DIM)
            xnext = *(const float2*)(g_xT + (size_t)(t + 1) * B_DIM + rowbase + rA);

        // ---- preload full h vector for both rows (raw (hA,hB) pairs) ----
        u64 h2[H];
#pragma unroll
        for (int u = 0; u < H; ++u)
            h2[u] = *(const u64*)&h_s[cur][u][rA];   // LDS.64, conflict-free

        // ---- out[t-1] = W2 . h + b2 : warp 0 reuses its h2 registers ----
        if (up == 0 && t > 0) {
            u64 oacc = pk(b2_s, b2_s);
#pragma unroll
            for (int u = 0; u < H; ++u)
                oacc = fma2(w2p[u], h2[u], oacc);    // (outA, outB)
            float o0, o1; upk(oacc, o0, o1);
            *(float2*)(g_outT + (size_t)(t - 1) * B_DIM + rowbase + rA) =
                make_float2(o0, o1);
        }

        // ---- gates for units {2up, 2up+1}, rows A and B ----
        u64 xpA = pk(xv.x, xv.x), xpB = pk(xv.y, xv.y);
        u64 iA = fma2(xpA, u_i, v_i), iB = fma2(xpB, u_i, v_i);
        u64 fA = fma2(xpA, u_f, v_f), fB = fma2(xpB, u_f, v_f);
        u64 gA = fma2(xpA, u_g, v_g), gB = fma2(xpB, u_g, v_g);
        u64 oA = fma2(xpA, u_o, v_o), oB = fma2(xpB, u_o, v_o);

#pragma unroll
        for (int u = 0; u < H; ++u) {
            float hA, hB; upk(h2[u], hA, hB);
            u64 hpA = pk(hA, hA), hpB = pk(hB, hB);
            ulonglong2 wa = *(const ulonglong2*)&WP_s[u][up * 4];      // (w_i, w_f)
            ulonglong2 wb = *(const ulonglong2*)&WP_s[u][up * 4 + 2];  // (w_g, w_o)
            iA = fma2(wa.x, hpA, iA);  iB = fma2(wa.x, hpB, iB);
            fA = fma2(wa.y, hpA, fA);  fB = fma2(wa.y, hpB, fB);
            gA = fma2(wb.x, hpA, gA);  gB = fma2(wb.x, hpB, gB);
            oA = fma2(wb.y, hpA, oA);  oB = fma2(wb.y, hpB, oB);
        }

        // ---- cell updates in-warp: 4 cells = (u0,u1) x (rowA,rowB) ----
        float i0A, i1A, f0A, f1A, g0A, g1A, o0A, o1A;
        float i0B, i1B, f0B, f1B, g0B, g1B, o0B, o1B;
        upk(iA, i0A, i1A); upk(fA, f0A, f1A); upk(gA, g0A, g1A); upk(oA, o0A, o1A);
        upk(iB, i0B, i1B); upk(fB, f0B, f1B); upk(gB, g0B, g1B); upk(oB, o0B, o1B);
        float c0A, c1A, c0B, c1B;
        upk(cA, c0A, c1A); upk(cB, c0B, c1B);
        float h0A, h1A, h0B, h1B;
        cell(i0A, f0A, g0A, o0A, c0A, h0A);
        cell(i1A, f1A, g1A, o1A, c1A, h1A);
        cell(i0B, f0B, g0B, o0B, c0B, h0B);
        cell(i1B, f1B, g1B, o1B, c1B, h1B);
        cA = pk(c0A, c1A); cB = pk(c0B, c1B);

        // publish h: unit 2up gets (h0A at rA, h0B at rA+1); unit 2up+1 likewise
        *(u64*)&h_s[nxt][2 * up    ][rA] = pk(h0A, h0B);   // STS.64
        *(u64*)&h_s[nxt][2 * up + 1][rA] = pk(h1A, h1B);

        // ---- single barrier: publish h, protect buffer swap ----
        __syncthreads();

        xv = xnext;
    }

    // final output row: out[T-1] from buffer (T_DIM & 1)
    if (up == 0) {
        const int cur = T_DIM & 1;
        u64 oacc = pk(b2_s, b2_s);
#pragma unroll
        for (int u = 0; u < H; ++u)
            oacc = fma2(w2p[u], *(const u64*)&h_s[cur][u][rA], oacc);
        float o0, o1; upk(oacc, o0, o1);
        *(float2*)(g_outT + (size_t)(T_DIM - 1) * B_DIM + rowbase + rA) =
            make_float2(o0, o1);
    }
}

// ---------------- launcher ----------------
extern "C" void kernel_launch(void* const* d_in, const int* in_sizes, int n_in,
                              void* d_out, int out_size)
{
    const float* x    = (const float*)d_in[0];
    const float* W1   = (const float*)d_in[1];
    const float* b1   = (const float*)d_in[2];
    const float* W_ih = (const float*)d_in[3];
    const float* W_hh = (const float*)d_in[4];
    const float* b_ih = (const float*)d_in[5];
    const float* b_hh = (const float*)d_in[6];
    const float* W2   = (const float*)d_in[7];
    const float* b2   = (const float*)d_in[8];
    float* out = (float*)d_out;

    (void)in_sizes; (void)n_in; (void)out_size;

    // x[B][T] -> g_xT[T][B]
    transpose_in<<<dim3(T_DIM / 32, B_DIM / 32), dim3(32, 8)>>>(x);

    // recurrent scan: 128 CTAs x 320 threads, 2 rows/lane, unit-pair packed
    lstm_kernel<<<B_DIM / CTA_ROWS, NTHR>>>(W1, b1, W_ih, W_hh, b_ih, b_hh, W2, b2);

    // g_outT[T][B] -> out[B][T]
    transpose_out<<<dim3(B_DIM / 32, T_DIM / 32), dim3(32, 8)>>>(out);
}